// round 1
// baseline (speedup 1.0000x reference)
#include <cuda_runtime.h>

// Problem constants (fixed by the reference)
#define BS   16384
#define DIN  512
#define MID  1024
#define OUTC 512
#define K1   1024     // gemm1 K  (= din * kernel)
#define K2   3072     // gemm2 K  (= mid*kernel + din*kernel)
#define EPSV 1e-5f

// Scratch: __device__ globals (no allocs allowed)
__device__ float g_w1t[(size_t)K1 * MID];        // [k][n], de-interleaved w1^T
__device__ float g_w2t[(size_t)K2 * OUTC];       // [k][n], combined w2/w_skip^T
__device__ float g_h1 [(size_t)BS * MID];        // stage-1 activations

// ---------------------------------------------------------------------------
// Weight prep: de-interleave even/odd columns and transpose to [k][n]
// ---------------------------------------------------------------------------
__global__ void prep_w1_kernel(const float* __restrict__ w1) {
    int idx = blockIdx.x * blockDim.x + threadIdx.x;    // n*K1 + k, k fast
    if (idx >= MID * K1) return;
    int n = idx >> 10;          // /1024
    int k = idx & 1023;
    int src = (k < 512) ? (2 * k) : (2 * (k - 512) + 1);
    g_w1t[(size_t)k * MID + n] = w1[(size_t)n * 1024 + src];
}

__global__ void prep_w2_kernel(const float* __restrict__ w2,
                               const float* __restrict__ wsk) {
    int idx = blockIdx.x * blockDim.x + threadIdx.x;    // n*K2 + k, k fast
    if (idx >= OUTC * K2) return;
    int n = idx / K2;
    int k = idx - n * K2;
    float v;
    if (k < 1024)      v = w2 [(size_t)n * 2048 + 2 * k];
    else if (k < 2048) v = w2 [(size_t)n * 2048 + 2 * (k - 1024) + 1];
    else if (k < 2560) v = wsk[(size_t)n * 1024 + 2 * (k - 2048)];
    else               v = wsk[(size_t)n * 1024 + 2 * (k - 2560) + 1];
    g_w2t[(size_t)k * OUTC + n] = v;
}

// ---------------------------------------------------------------------------
// Packed f32x2 helpers (Blackwell: 2x fp32 FMA throughput vs scalar FFMA)
// ---------------------------------------------------------------------------
__device__ __forceinline__ unsigned long long packdup(float v) {
    unsigned long long r;
    asm("mov.b64 %0, {%1, %1};" : "=l"(r) : "f"(v));
    return r;
}
__device__ __forceinline__ void fma2(unsigned long long& d,
                                     unsigned long long a,
                                     unsigned long long b) {
    asm("fma.rn.f32x2 %0, %1, %2, %0;" : "+l"(d) : "l"(a), "l"(b));
}
__device__ __forceinline__ float2 unpack2(unsigned long long v) {
    float2 f;
    asm("mov.b64 {%0, %1}, %2;" : "=f"(f.x), "=f"(f.y) : "l"(v));
    return f;
}

// ---------------------------------------------------------------------------
// GEMM tiling: 128x128 block, BK=16, 256 threads, 8x8 per thread
// ---------------------------------------------------------------------------
#define BM  128
#define BN  128
#define BKT 16
#define TM  8
#define TN  8

// GEMM1: h1 = BN1(relu([q1_0 | x] @ w1t + b1)),  M=BS, N=MID, K=K1
__global__ __launch_bounds__(256, 2)
void gemm1_kernel(const float* __restrict__ q1, const float* __restrict__ x,
                  const float* __restrict__ b1,
                  const float* __restrict__ s1, const float* __restrict__ bb1,
                  const float* __restrict__ m1, const float* __restrict__ v1)
{
    __shared__ float As[BKT][BM];
    __shared__ float Bs[BKT][BN];

    const int tid = threadIdx.x;
    const int tx = tid & 15;     // N direction (x16)
    const int ty = tid >> 4;     // M direction (x16)
    const int bm = blockIdx.x * BM;
    const int bn = blockIdx.y * BN;

    unsigned long long c2[TM][TN / 2];
#pragma unroll
    for (int i = 0; i < TM; i++)
#pragma unroll
        for (int j = 0; j < TN / 2; j++) c2[i][j] = 0ull;

    const int ar = tid >> 2;           // 0..63
    const int ac = (tid & 3) << 2;     // 0,4,8,12
    const int br = tid >> 5;           // 0..7
    const int bc = (tid & 31) << 2;    // 0..124

    for (int k0 = 0; k0 < K1; k0 += BKT) {
        // segment select: k<512 -> conv1_queue[0], else x (interleave resolved in w1t)
        const float* ab = (k0 < 512) ? (q1 + (size_t)bm * DIN + k0)
                                     : (x  + (size_t)bm * DIN + (k0 - 512));
#pragma unroll
        for (int i = 0; i < 2; i++) {
            int r = ar + i * 64;
            float4 v = *(const float4*)(ab + (size_t)r * DIN + ac);
            As[ac + 0][r] = v.x; As[ac + 1][r] = v.y;
            As[ac + 2][r] = v.z; As[ac + 3][r] = v.w;
        }
#pragma unroll
        for (int i = 0; i < 2; i++) {
            int r = br + i * 8;
            *(float4*)&Bs[r][bc] =
                *(const float4*)(g_w1t + (size_t)(k0 + r) * MID + bn + bc);
        }
        __syncthreads();

#pragma unroll
        for (int kk = 0; kk < BKT; kk++) {
            unsigned long long b2r[TN / 2], a2r[TM];
#pragma unroll
            for (int j = 0; j < TN / 2; j++)
                b2r[j] = *(const unsigned long long*)&Bs[kk][tx * TN + 2 * j];
#pragma unroll
            for (int i = 0; i < TM; i++)
                a2r[i] = packdup(As[kk][ty * TM + i]);
#pragma unroll
            for (int i = 0; i < TM; i++)
#pragma unroll
                for (int j = 0; j < TN / 2; j++)
                    fma2(c2[i][j], a2r[i], b2r[j]);
        }
        __syncthreads();
    }

    // epilogue: +bias, relu, BN(eval), store to g_h1
#pragma unroll
    for (int j = 0; j < TN / 2; j++) {
        int n = bn + tx * TN + 2 * j;
        float sc0 = s1[n]     * rsqrtf(v1[n]     + EPSV);
        float sc1 = s1[n + 1] * rsqrtf(v1[n + 1] + EPSV);
        float bi0 = bb1[n]     - m1[n]     * sc0;
        float bi1 = bb1[n + 1] - m1[n + 1] * sc1;
        float bs0 = b1[n], bs1 = b1[n + 1];
#pragma unroll
        for (int i = 0; i < TM; i++) {
            float2 c = unpack2(c2[i][j]);
            float h0 = fmaxf(c.x + bs0, 0.f);
            float h1 = fmaxf(c.y + bs1, 0.f);
            float2 o = make_float2(h0 * sc0 + bi0, h1 * sc1 + bi1);
            int m = bm + ty * TM + i;
            *(float2*)&g_h1[(size_t)m * MID + n] = o;
        }
    }
}

// GEMM2: out = BN2(relu([q2_0 | h1 | q1_0 | x] @ w2t + b2 + bsk)), N=OUTC, K=K2
__global__ __launch_bounds__(256, 2)
void gemm2_kernel(const float* __restrict__ q2, const float* __restrict__ q1,
                  const float* __restrict__ x,
                  const float* __restrict__ b2, const float* __restrict__ bsk,
                  const float* __restrict__ s2, const float* __restrict__ bb2,
                  const float* __restrict__ m2, const float* __restrict__ v2,
                  float* __restrict__ out)
{
    __shared__ float As[BKT][BM];
    __shared__ float Bs[BKT][BN];

    const int tid = threadIdx.x;
    const int tx = tid & 15;
    const int ty = tid >> 4;
    const int bm = blockIdx.x * BM;
    const int bn = blockIdx.y * BN;

    unsigned long long c2[TM][TN / 2];
#pragma unroll
    for (int i = 0; i < TM; i++)
#pragma unroll
        for (int j = 0; j < TN / 2; j++) c2[i][j] = 0ull;

    const int ar = tid >> 2;
    const int ac = (tid & 3) << 2;
    const int br = tid >> 5;
    const int bc = (tid & 31) << 2;

    for (int k0 = 0; k0 < K2; k0 += BKT) {
        const float* ab;
        int stride;
        if (k0 < 1024)      { ab = q2   + (size_t)bm * 1024 + k0;          stride = 1024; }
        else if (k0 < 2048) { ab = g_h1 + (size_t)bm * 1024 + (k0 - 1024); stride = 1024; }
        else if (k0 < 2560) { ab = q1   + (size_t)bm * 512  + (k0 - 2048); stride = 512;  }
        else                { ab = x    + (size_t)bm * 512  + (k0 - 2560); stride = 512;  }
#pragma unroll
        for (int i = 0; i < 2; i++) {
            int r = ar + i * 64;
            float4 v = *(const float4*)(ab + (size_t)r * stride + ac);
            As[ac + 0][r] = v.x; As[ac + 1][r] = v.y;
            As[ac + 2][r] = v.z; As[ac + 3][r] = v.w;
        }
#pragma unroll
        for (int i = 0; i < 2; i++) {
            int r = br + i * 8;
            *(float4*)&Bs[r][bc] =
                *(const float4*)(g_w2t + (size_t)(k0 + r) * OUTC + bn + bc);
        }
        __syncthreads();

#pragma unroll
        for (int kk = 0; kk < BKT; kk++) {
            unsigned long long b2r[TN / 2], a2r[TM];
#pragma unroll
            for (int j = 0; j < TN / 2; j++)
                b2r[j] = *(const unsigned long long*)&Bs[kk][tx * TN + 2 * j];
#pragma unroll
            for (int i = 0; i < TM; i++)
                a2r[i] = packdup(As[kk][ty * TM + i]);
#pragma unroll
            for (int i = 0; i < TM; i++)
#pragma unroll
                for (int j = 0; j < TN / 2; j++)
                    fma2(c2[i][j], a2r[i], b2r[j]);
        }
        __syncthreads();
    }

#pragma unroll
    for (int j = 0; j < TN / 2; j++) {
        int n = bn + tx * TN + 2 * j;
        float sc0 = s2[n]     * rsqrtf(v2[n]     + EPSV);
        float sc1 = s2[n + 1] * rsqrtf(v2[n + 1] + EPSV);
        float bi0 = bb2[n]     - m2[n]     * sc0;
        float bi1 = bb2[n + 1] - m2[n + 1] * sc1;
        float bs0 = b2[n] + bsk[n];
        float bs1 = b2[n + 1] + bsk[n + 1];
#pragma unroll
        for (int i = 0; i < TM; i++) {
            float2 c = unpack2(c2[i][j]);
            float h0 = fmaxf(c.x + bs0, 0.f);
            float h1 = fmaxf(c.y + bs1, 0.f);
            float2 o = make_float2(h0 * sc0 + bi0, h1 * sc1 + bi1);
            int m = bm + ty * TM + i;
            *(float2*)&out[(size_t)m * OUTC + n] = o;
        }
    }
}

// ---------------------------------------------------------------------------
extern "C" void kernel_launch(void* const* d_in, const int* in_sizes, int n_in,
                              void* d_out, int out_size) {
    const float* x   = (const float*)d_in[0];
    const float* q1  = (const float*)d_in[1];   // conv1_queue; slice [0] at offset 0
    const float* q2  = (const float*)d_in[2];   // conv2_queue; slice [0] at offset 0
    const float* w1  = (const float*)d_in[3];
    const float* b1  = (const float*)d_in[4];
    const float* w2  = (const float*)d_in[5];
    const float* b2  = (const float*)d_in[6];
    const float* wsk = (const float*)d_in[7];
    const float* bsk = (const float*)d_in[8];
    const float* s1  = (const float*)d_in[9];
    const float* bb1 = (const float*)d_in[10];
    const float* m1  = (const float*)d_in[11];
    const float* v1  = (const float*)d_in[12];
    const float* s2  = (const float*)d_in[13];
    const float* bb2 = (const float*)d_in[14];
    const float* m2  = (const float*)d_in[15];
    const float* v2  = (const float*)d_in[16];
    float* out = (float*)d_out;

    prep_w1_kernel<<<(MID * K1 + 255) / 256, 256>>>(w1);
    prep_w2_kernel<<<(OUTC * K2 + 255) / 256, 256>>>(w2, wsk);
    gemm1_kernel<<<dim3(BS / BM, MID / BN), 256>>>(q1, x, b1, s1, bb1, m1, v1);
    gemm2_kernel<<<dim3(BS / BM, OUTC / BN), 256>>>(q2, q1, x, b2, bsk,
                                                    s2, bb2, m2, v2, out);
}

// round 3
// speedup vs baseline: 2.2278x; 2.2278x over previous
#include <cuda_runtime.h>
#include <cuda_bf16.h>
#include <cstdint>

#define BS   16384
#define EPSV 1e-5f

// ---------------------------------------------------------------------------
// Device scratch (no allocs allowed)
// ---------------------------------------------------------------------------
__device__ __nv_bfloat16 g_a1hi[(size_t)BS * 1024];   // [b][k] : q1_0 | x
__device__ __nv_bfloat16 g_a1lo[(size_t)BS * 1024];
__device__ __nv_bfloat16 g_a2hi[(size_t)BS * 2048];   // [b][k] : q2_0 | h1
__device__ __nv_bfloat16 g_a2lo[(size_t)BS * 2048];
__device__ __nv_bfloat16 g_w1hi[1024 * 1024];         // [n][k] de-interleaved
__device__ __nv_bfloat16 g_w1lo[1024 * 1024];
__device__ __nv_bfloat16 g_w2hi[512 * 3072];          // [n][k] w2|wsk combined
__device__ __nv_bfloat16 g_w2lo[512 * 3072];

// ---------------------------------------------------------------------------
// Helpers
// ---------------------------------------------------------------------------
__device__ __forceinline__ uint32_t s2u(const void* p) {
    uint32_t a;
    asm("{ .reg .u64 t; cvta.to.shared.u64 t, %1; cvt.u32.u64 %0, t; }"
        : "=r"(a) : "l"(p));
    return a;
}
__device__ __forceinline__ void cp16(uint32_t saddr, const void* gptr) {
    asm volatile("cp.async.ca.shared.global [%0], [%1], 16;"
                 :: "r"(saddr), "l"(__cvta_generic_to_global(gptr)) : "memory");
}
#define CP_COMMIT() asm volatile("cp.async.commit_group;" ::: "memory")
#define CP_WAIT(n)  asm volatile("cp.async.wait_group %0;" :: "n"(n) : "memory")

__device__ __forceinline__ void ldmx4(uint32_t* r, uint32_t addr) {
    asm volatile("ldmatrix.sync.aligned.m8n8.x4.shared.b16 {%0,%1,%2,%3}, [%4];"
                 : "=r"(r[0]), "=r"(r[1]), "=r"(r[2]), "=r"(r[3]) : "r"(addr));
}
__device__ __forceinline__ void mma16816(float* d, const uint32_t* a,
                                         uint32_t b0, uint32_t b1) {
    asm volatile(
        "mma.sync.aligned.m16n8k16.row.col.f32.bf16.bf16.f32 "
        "{%0,%1,%2,%3}, {%4,%5,%6,%7}, {%8,%9}, {%0,%1,%2,%3};"
        : "+f"(d[0]), "+f"(d[1]), "+f"(d[2]), "+f"(d[3])
        : "r"(a[0]), "r"(a[1]), "r"(a[2]), "r"(a[3]), "r"(b0), "r"(b1));
}
__device__ __forceinline__ void split2(float v, __nv_bfloat16& h, __nv_bfloat16& l) {
    h = __float2bfloat16_rn(v);
    l = __float2bfloat16_rn(v - __bfloat162float(h));
}
__device__ __forceinline__ uint32_t pk2(__nv_bfloat16 a, __nv_bfloat16 b) {
    __nv_bfloat162 t(a, b);
    return *reinterpret_cast<uint32_t*>(&t);
}

// ---------------------------------------------------------------------------
// Prep kernels
// ---------------------------------------------------------------------------
__global__ void conv_a1_kernel(const float* __restrict__ q1, const float* __restrict__ x) {
    int idx = blockIdx.x * 256 + threadIdx.x;       // 4 elems each
    int b = idx >> 8;
    int k4 = (idx & 255) << 2;
    const float* src = (k4 < 512) ? (q1 + (size_t)b * 512 + k4)
                                  : (x  + (size_t)b * 512 + k4 - 512);
    float4 v = *(const float4*)src;
    __nv_bfloat16 h0,h1,h2,h3,l0,l1,l2,l3;
    split2(v.x,h0,l0); split2(v.y,h1,l1); split2(v.z,h2,l2); split2(v.w,h3,l3);
    size_t o = (size_t)b * 1024 + k4;
    *(uint2*)(g_a1hi + o) = make_uint2(pk2(h0,h1), pk2(h2,h3));
    *(uint2*)(g_a1lo + o) = make_uint2(pk2(l0,l1), pk2(l2,l3));
}
__global__ void conv_a2_kernel(const float* __restrict__ q2) {
    int idx = blockIdx.x * 256 + threadIdx.x;
    int b = idx >> 8;
    int k4 = (idx & 255) << 2;
    float4 v = *(const float4*)(q2 + (size_t)b * 1024 + k4);
    __nv_bfloat16 h0,h1,h2,h3,l0,l1,l2,l3;
    split2(v.x,h0,l0); split2(v.y,h1,l1); split2(v.z,h2,l2); split2(v.w,h3,l3);
    size_t o = (size_t)b * 2048 + k4;
    *(uint2*)(g_a2hi + o) = make_uint2(pk2(h0,h1), pk2(h2,h3));
    *(uint2*)(g_a2lo + o) = make_uint2(pk2(l0,l1), pk2(l2,l3));
}
__global__ void prep_w1_kernel(const float* __restrict__ w1) {
    int idx = blockIdx.x * 256 + threadIdx.x;       // n*1024 + k
    int n = idx >> 10, k = idx & 1023;
    int src = (k < 512) ? (2 * k) : (2 * (k - 512) + 1);
    float v = w1[(size_t)n * 1024 + src];
    __nv_bfloat16 h, l; split2(v, h, l);
    g_w1hi[idx] = h; g_w1lo[idx] = l;
}
__global__ void prep_w2_kernel(const float* __restrict__ w2, const float* __restrict__ wsk) {
    int idx = blockIdx.x * 256 + threadIdx.x;       // n*3072 + k
    int n = idx / 3072, k = idx - n * 3072;
    float v;
    if (k < 1024)      v = w2 [(size_t)n * 2048 + 2 * k];
    else if (k < 2048) v = w2 [(size_t)n * 2048 + 2 * (k - 1024) + 1];
    else if (k < 2560) v = wsk[(size_t)n * 1024 + 2 * (k - 2048)];
    else               v = wsk[(size_t)n * 1024 + 2 * (k - 2560) + 1];
    __nv_bfloat16 h, l; split2(v, h, l);
    g_w2hi[idx] = h; g_w2lo[idx] = l;
}

// ---------------------------------------------------------------------------
// mma.sync GEMM: CTA 128x128, K-chunk 32, 8 warps (warp tile 64x32),
// double-buffered cp.async. SMEM rows padded to 80B (conflict-free ldmatrix).
// Stage layout: Ahi[128][40] | Alo | Bhi[128][40] | Blo  (40960 B / stage)
// ---------------------------------------------------------------------------
#define PITCH      40          // bf16 elems per smem row (80 B)
#define MAT_BYTES  (128 * PITCH * 2)
#define STAGE_B    (4 * MAT_BYTES)
#define SMEM_TOTAL (2 * STAGE_B)

template<int G>
__global__ __launch_bounds__(256, 1)
void mma_kernel(const float* __restrict__ e0, const float* __restrict__ e1,
                const float* __restrict__ e2, const float* __restrict__ e3,
                const float* __restrict__ e4, const float* __restrict__ e5,
                float* __restrict__ outp)
{
    extern __shared__ char smem[];
    const uint32_t sbase = s2u(smem);
    const int tid  = threadIdx.x;
    const int wid  = tid >> 5, lane = tid & 31;
    const int bm   = blockIdx.x * 128;
    const int bn   = blockIdx.y * 128;
    const int wm   = (wid & 1) * 64;      // warp M offset
    const int wn   = (wid >> 1) * 32;     // warp N offset
    constexpr int NC = (G == 1) ? 32 : 96;

    float acc[4][4][4];
#pragma unroll
    for (int i = 0; i < 4; i++)
#pragma unroll
        for (int j = 0; j < 4; j++)
#pragma unroll
            for (int k = 0; k < 4; k++) acc[i][j][k] = 0.f;

    // ---- stage loader (cp.async) ----
    const int lrow = tid >> 2;            // 0..63 (x2 iters -> 128 rows)
    const int lch  = tid & 3;             // 16B chunk within 64B of k-data
    auto load_stage = [&](int s, int c) {
        const int k0 = c * 32;
        const __nv_bfloat16 *Ahi, *Alo;
        int astr, acol;
        if (G == 1)       { Ahi = g_a1hi; Alo = g_a1lo; astr = 1024; acol = k0; }
        else if (k0 < 2048){ Ahi = g_a2hi; Alo = g_a2lo; astr = 2048; acol = k0; }
        else              { Ahi = g_a1hi; Alo = g_a1lo; astr = 1024; acol = k0 - 2048; }
        const __nv_bfloat16* Bhi = (G == 1) ? g_w1hi : g_w2hi;
        const __nv_bfloat16* Blo = (G == 1) ? g_w1lo : g_w2lo;
        const int bstr = (G == 1) ? 1024 : 3072;
        const uint32_t st = sbase + s * STAGE_B;
#pragma unroll
        for (int it = 0; it < 2; it++) {
            const int row = lrow + it * 64;
            const uint32_t so = row * 80 + lch * 16;
            const size_t ga = (size_t)(bm + row) * astr + acol + lch * 8;
            const size_t gb = (size_t)(bn + row) * bstr + k0   + lch * 8;
            cp16(st + so,                 Ahi + ga);
            cp16(st + so + MAT_BYTES,     Alo + ga);
            cp16(st + so + 2 * MAT_BYTES, Bhi + gb);
            cp16(st + so + 3 * MAT_BYTES, Blo + gb);
        }
    };

    // per-thread ldmatrix base offsets (lane -> row/chunk mapping)
    const int mrow = lane & 15, msel = lane >> 4;
    const uint32_t aoff = (wm + mrow) * 80 + msel * 16;
    const uint32_t boff = (wn + mrow) * 80 + msel * 16;

    load_stage(0, 0);
    CP_COMMIT();

    for (int c = 0; c < NC; c++) {
        if (c + 1 < NC) {
            load_stage((c + 1) & 1, c + 1);
            CP_COMMIT();
            CP_WAIT(1);
        } else {
            CP_WAIT(0);
        }
        __syncthreads();

        const uint32_t st = sbase + (c & 1) * STAGE_B;
#pragma unroll
        for (int ks = 0; ks < 2; ks++) {               // two k16 substeps
            const uint32_t kadd = ks * 32;             // 16 bf16 = 32 B
            uint32_t bh[2][4], bl[2][4];
#pragma unroll
            for (int p = 0; p < 2; p++) {              // two 16n x 16k blocks
                ldmx4(bh[p], st + 2 * MAT_BYTES + boff + p * 16 * 80 + kadd);
                ldmx4(bl[p], st + 3 * MAT_BYTES + boff + p * 16 * 80 + kadd);
            }
#pragma unroll
            for (int mt = 0; mt < 4; mt++) {
                uint32_t ah[4], al[4];
                ldmx4(ah, st + aoff + mt * 16 * 80 + kadd);
                ldmx4(al, st + MAT_BYTES + aoff + mt * 16 * 80 + kadd);
#pragma unroll
                for (int nt = 0; nt < 4; nt++) {
                    const int p = nt >> 1, o = nt & 1;
                    mma16816(acc[mt][nt], ah, bh[p][o], bh[p][2 + o]);
                    mma16816(acc[mt][nt], ah, bl[p][o], bl[p][2 + o]);
                    mma16816(acc[mt][nt], al, bh[p][o], bh[p][2 + o]);
                }
            }
        }
        __syncthreads();
    }

    // ---- epilogue: stage per-column params, then write ----
    if (tid < 128) {
        const int n = bn + tid;
        float sc, bi, bc;
        if (G == 1) { sc = e1[n] * rsqrtf(e4[n] + EPSV); bi = e2[n] - e3[n] * sc; bc = e0[n]; }
        else        { sc = e2[n] * rsqrtf(e5[n] + EPSV); bi = e3[n] - e4[n] * sc; bc = e0[n] + e1[n]; }
        ((float*)smem)[tid]       = sc;
        ((float*)smem)[128 + tid] = bi;
        ((float*)smem)[256 + tid] = bc;
    }
    __syncthreads();
    const float* scp = (const float*)smem;
    const float* bip = scp + 128;
    const float* bcp = scp + 256;

    const int g  = lane >> 2, tg = lane & 3;
#pragma unroll
    for (int mt = 0; mt < 4; mt++) {
#pragma unroll
        for (int nt = 0; nt < 4; nt++) {
            const int nl = wn + nt * 8 + 2 * tg;       // CTA-local col (even)
            const float s0 = scp[nl], s1v = scp[nl + 1];
            const float i0 = bip[nl], i1 = bip[nl + 1];
            const float c0 = bcp[nl], c1 = bcp[nl + 1];
#pragma unroll
            for (int half = 0; half < 2; half++) {
                const int m = bm + wm + mt * 16 + g + half * 8;
                const float v0 = fmaxf(acc[mt][nt][2 * half]     + c0, 0.f) * s0  + i0;
                const float v1 = fmaxf(acc[mt][nt][2 * half + 1] + c1, 0.f) * s1v + i1;
                if (G == 1) {
                    __nv_bfloat16 h0, l0, h1, l1;
                    split2(v0, h0, l0); split2(v1, h1, l1);
                    const size_t o = (size_t)m * 2048 + 1024 + bn + nl;
                    *(uint32_t*)(g_a2hi + o) = pk2(h0, h1);
                    *(uint32_t*)(g_a2lo + o) = pk2(l0, l1);
                } else {
                    *(float2*)(outp + (size_t)m * 512 + bn + nl) = make_float2(v0, v1);
                }
            }
        }
    }
}

// ---------------------------------------------------------------------------
extern "C" void kernel_launch(void* const* d_in, const int* in_sizes, int n_in,
                              void* d_out, int out_size) {
    const float* x   = (const float*)d_in[0];
    const float* q1  = (const float*)d_in[1];
    const float* q2  = (const float*)d_in[2];
    const float* w1  = (const float*)d_in[3];
    const float* b1  = (const float*)d_in[4];
    const float* w2  = (const float*)d_in[5];
    const float* b2  = (const float*)d_in[6];
    const float* wsk = (const float*)d_in[7];
    const float* bsk = (const float*)d_in[8];
    const float* s1  = (const float*)d_in[9];
    const float* bb1 = (const float*)d_in[10];
    const float* m1  = (const float*)d_in[11];
    const float* v1  = (const float*)d_in[12];
    const float* s2  = (const float*)d_in[13];
    const float* bb2 = (const float*)d_in[14];
    const float* m2  = (const float*)d_in[15];
    const float* v2  = (const float*)d_in[16];
    float* out = (float*)d_out;

    cudaFuncSetAttribute(mma_kernel<1>, cudaFuncAttributeMaxDynamicSharedMemorySize, SMEM_TOTAL);
    cudaFuncSetAttribute(mma_kernel<2>, cudaFuncAttributeMaxDynamicSharedMemorySize, SMEM_TOTAL);

    prep_w1_kernel<<<1024 * 1024 / 256, 256>>>(w1);
    prep_w2_kernel<<<512 * 3072 / 256, 256>>>(w2, wsk);
    conv_a1_kernel<<<BS * 1024 / 4 / 256, 256>>>(q1, x);
    conv_a2_kernel<<<BS * 1024 / 4 / 256, 256>>>(q2);

    mma_kernel<1><<<dim3(BS / 128, 8), 256, SMEM_TOTAL>>>(b1, s1, bb1, m1, v1, v1, nullptr);
    mma_kernel<2><<<dim3(BS / 128, 4), 256, SMEM_TOTAL>>>(b2, bsk, s2, bb2, m2, v2, out);
}

// round 4
// speedup vs baseline: 3.1228x; 1.4017x over previous
#include <cuda_runtime.h>
#include <cuda_fp16.h>
#include <cstdint>

#define BS   16384
#define EPSV 1e-5f

// ---------------------------------------------------------------------------
// Device scratch (no allocs allowed)
// ---------------------------------------------------------------------------
__device__ __half g_a1[(size_t)BS * 1024];   // [b][k] : q1_0 | x   (fp16)
__device__ __half g_a2[(size_t)BS * 2048];   // [b][k] : q2_0 | h1  (fp16)
__device__ __half g_w1hi[1024 * 1024];       // [n][k] de-interleaved
__device__ __half g_w1lo[1024 * 1024];
__device__ __half g_w2hi[512 * 3072];        // [n][k] w2|wsk combined
__device__ __half g_w2lo[512 * 3072];

// ---------------------------------------------------------------------------
// Helpers
// ---------------------------------------------------------------------------
__device__ __forceinline__ uint32_t s2u(const void* p) {
    uint32_t a;
    asm("{ .reg .u64 t; cvta.to.shared.u64 t, %1; cvt.u32.u64 %0, t; }"
        : "=r"(a) : "l"(p));
    return a;
}
__device__ __forceinline__ void cp16(uint32_t saddr, const void* gptr) {
    asm volatile("cp.async.cg.shared.global [%0], [%1], 16;"
                 :: "r"(saddr), "l"(__cvta_generic_to_global(gptr)) : "memory");
}
#define CP_COMMIT() asm volatile("cp.async.commit_group;" ::: "memory")
#define CP_WAIT(n)  asm volatile("cp.async.wait_group %0;" :: "n"(n) : "memory")

__device__ __forceinline__ void ldmx4(uint32_t* r, uint32_t addr) {
    asm volatile("ldmatrix.sync.aligned.m8n8.x4.shared.b16 {%0,%1,%2,%3}, [%4];"
                 : "=r"(r[0]), "=r"(r[1]), "=r"(r[2]), "=r"(r[3]) : "r"(addr));
}
__device__ __forceinline__ void mma16816(float* d, const uint32_t* a,
                                         uint32_t b0, uint32_t b1) {
    asm volatile(
        "mma.sync.aligned.m16n8k16.row.col.f32.f16.f16.f32 "
        "{%0,%1,%2,%3}, {%4,%5,%6,%7}, {%8,%9}, {%0,%1,%2,%3};"
        : "+f"(d[0]), "+f"(d[1]), "+f"(d[2]), "+f"(d[3])
        : "r"(a[0]), "r"(a[1]), "r"(a[2]), "r"(a[3]), "r"(b0), "r"(b1));
}
__device__ __forceinline__ uint32_t pk2h(__half a, __half b) {
    __half2 t(a, b);
    return *reinterpret_cast<uint32_t*>(&t);
}

// ---------------------------------------------------------------------------
// Prep kernels
// ---------------------------------------------------------------------------
__global__ void conv_a1_kernel(const float* __restrict__ q1, const float* __restrict__ x) {
    int idx = blockIdx.x * 256 + threadIdx.x;       // 4 elems each
    int b = idx >> 8;
    int k4 = (idx & 255) << 2;
    const float* src = (k4 < 512) ? (q1 + (size_t)b * 512 + k4)
                                  : (x  + (size_t)b * 512 + k4 - 512);
    float4 v = *(const float4*)src;
    size_t o = (size_t)b * 1024 + k4;
    *(uint2*)(g_a1 + o) = make_uint2(pk2h(__float2half_rn(v.x), __float2half_rn(v.y)),
                                     pk2h(__float2half_rn(v.z), __float2half_rn(v.w)));
}
__global__ void conv_a2_kernel(const float* __restrict__ q2) {
    int idx = blockIdx.x * 256 + threadIdx.x;
    int b = idx >> 8;
    int k4 = (idx & 255) << 2;
    float4 v = *(const float4*)(q2 + (size_t)b * 1024 + k4);
    size_t o = (size_t)b * 2048 + k4;
    *(uint2*)(g_a2 + o) = make_uint2(pk2h(__float2half_rn(v.x), __float2half_rn(v.y)),
                                     pk2h(__float2half_rn(v.z), __float2half_rn(v.w)));
}
__device__ __forceinline__ void splith(float v, __half& h, __half& l) {
    h = __float2half_rn(v);
    l = __float2half_rn(v - __half2float(h));
}
__global__ void prep_w1_kernel(const float* __restrict__ w1) {
    int idx = blockIdx.x * 256 + threadIdx.x;       // n*1024 + k
    int n = idx >> 10, k = idx & 1023;
    int src = (k < 512) ? (2 * k) : (2 * (k - 512) + 1);
    float v = w1[(size_t)n * 1024 + src];
    __half h, l; splith(v, h, l);
    g_w1hi[idx] = h; g_w1lo[idx] = l;
}
__global__ void prep_w2_kernel(const float* __restrict__ w2, const float* __restrict__ wsk) {
    int idx = blockIdx.x * 256 + threadIdx.x;       // n*3072 + k
    int n = idx / 3072, k = idx - n * 3072;
    float v;
    if (k < 1024)      v = w2 [(size_t)n * 2048 + 2 * k];
    else if (k < 2048) v = w2 [(size_t)n * 2048 + 2 * (k - 1024) + 1];
    else if (k < 2560) v = wsk[(size_t)n * 1024 + 2 * (k - 2048)];
    else               v = wsk[(size_t)n * 1024 + 2 * (k - 2560) + 1];
    __half h, l; splith(v, h, l);
    g_w2hi[idx] = h; g_w2lo[idx] = l;
}

// ---------------------------------------------------------------------------
// mma.sync GEMM: CTA 256x128, K-chunk 32, 16 warps (warp tile 64x32),
// 3-stage cp.async pipeline, one __syncthreads per chunk.
// Stage: A[256][40] | Bhi[128][40] | Blo[128][40]  (40960 B/stage, pitch 80B)
// ---------------------------------------------------------------------------
#define PITCH_B    80
#define A_BYTES    (256 * PITCH_B)
#define Bm_BYTES   (128 * PITCH_B)
#define STAGE_B    (A_BYTES + 2 * Bm_BYTES)
#define SMEM_TOTAL (3 * STAGE_B)

template<int G>
__global__ __launch_bounds__(512, 1)
void mma_kernel(const float* __restrict__ e0, const float* __restrict__ e1,
                const float* __restrict__ e2, const float* __restrict__ e3,
                const float* __restrict__ e4, const float* __restrict__ e5,
                float* __restrict__ outp)
{
    extern __shared__ char smem[];
    const uint32_t sbase = s2u(smem);
    const int tid  = threadIdx.x;
    const int wid  = tid >> 5, lane = tid & 31;
    const int bm   = blockIdx.x * 256;
    const int bn   = blockIdx.y * 128;
    const int wm   = (wid & 3) * 64;      // warp M offset
    const int wn   = (wid >> 2) * 32;     // warp N offset
    constexpr int NC = (G == 1) ? 32 : 96;

    float acc[4][4][4];
#pragma unroll
    for (int i = 0; i < 4; i++)
#pragma unroll
        for (int j = 0; j < 4; j++)
#pragma unroll
            for (int k = 0; k < 4; k++) acc[i][j][k] = 0.f;

    // ---- stage loader: 512 threads, 4 cp.async each ----
    const int lrow = tid >> 2;            // 0..127
    const int lch  = tid & 3;             // 16B chunk of the 64B k-data
    auto load_stage = [&](int s, int c) {
        const int k0 = c * 32;
        const __half* Aa;
        int astr, acol;
        if (G == 1)        { Aa = g_a1; astr = 1024; acol = k0; }
        else if (k0 < 2048){ Aa = g_a2; astr = 2048; acol = k0; }
        else               { Aa = g_a1; astr = 1024; acol = k0 - 2048; }
        const __half* Bhi = (G == 1) ? g_w1hi : g_w2hi;
        const __half* Blo = (G == 1) ? g_w1lo : g_w2lo;
        const int bstr = (G == 1) ? 1024 : 3072;
        const uint32_t st = sbase + s * STAGE_B;
        const uint32_t so = lrow * PITCH_B + lch * 16;
        // A: rows lrow and lrow+128
        cp16(st + so,
             Aa + (size_t)(bm + lrow) * astr + acol + lch * 8);
        cp16(st + so + 128 * PITCH_B,
             Aa + (size_t)(bm + lrow + 128) * astr + acol + lch * 8);
        // B hi / lo: row lrow
        const size_t gb = (size_t)(bn + lrow) * bstr + k0 + lch * 8;
        cp16(st + A_BYTES + so,            Bhi + gb);
        cp16(st + A_BYTES + Bm_BYTES + so, Blo + gb);
    };

    // per-thread ldmatrix base offsets
    const int mrow = lane & 15, msel = lane >> 4;
    const uint32_t aoff = (wm + mrow) * PITCH_B + msel * 16;
    const uint32_t boff = (wn + mrow) * PITCH_B + msel * 16;

    load_stage(0, 0); CP_COMMIT();
    load_stage(1, 1); CP_COMMIT();

    int sc = 0;                            // stage index of chunk c
    for (int c = 0; c < NC; c++) {
        if (c + 1 < NC) { CP_WAIT(1); } else { CP_WAIT(0); }
        __syncthreads();
        if (c + 2 < NC) {
            int sn = sc + 2; if (sn >= 3) sn -= 3;
            load_stage(sn, c + 2);
            CP_COMMIT();
        }
        const uint32_t st = sbase + sc * STAGE_B;
#pragma unroll
        for (int ks = 0; ks < 2; ks++) {               // two k16 substeps
            const uint32_t kadd = ks * 32;             // 16 halfs = 32 B
            uint32_t bh[2][4], bl[2][4];
#pragma unroll
            for (int p = 0; p < 2; p++) {
                ldmx4(bh[p], st + A_BYTES + boff + p * 16 * PITCH_B + kadd);
                ldmx4(bl[p], st + A_BYTES + Bm_BYTES + boff + p * 16 * PITCH_B + kadd);
            }
#pragma unroll
            for (int mt = 0; mt < 4; mt++) {
                uint32_t ah[4];
                ldmx4(ah, st + aoff + mt * 16 * PITCH_B + kadd);
#pragma unroll
                for (int nt = 0; nt < 4; nt++) {
                    const int p = nt >> 1, o = nt & 1;
                    mma16816(acc[mt][nt], ah, bh[p][o], bh[p][2 + o]);
                    mma16816(acc[mt][nt], ah, bl[p][o], bl[p][2 + o]);
                }
            }
        }
        if (++sc == 3) sc = 0;
    }
    __syncthreads();

    // ---- epilogue: stage per-column params, then write ----
    if (tid < 128) {
        const int n = bn + tid;
        float s, bi, bc;
        if (G == 1) { s = e1[n] * rsqrtf(e4[n] + EPSV); bi = e2[n] - e3[n] * s; bc = e0[n]; }
        else        { s = e2[n] * rsqrtf(e5[n] + EPSV); bi = e3[n] - e4[n] * s; bc = e0[n] + e1[n]; }
        ((float*)smem)[tid]       = s;
        ((float*)smem)[128 + tid] = bi;
        ((float*)smem)[256 + tid] = bc;
    }
    __syncthreads();
    const float* scp = (const float*)smem;
    const float* bip = scp + 128;
    const float* bcp = scp + 256;

    const int g  = lane >> 2, tg = lane & 3;
#pragma unroll
    for (int mt = 0; mt < 4; mt++) {
#pragma unroll
        for (int nt = 0; nt < 4; nt++) {
            const int nl = wn + nt * 8 + 2 * tg;       // CTA-local col (even)
            const float s0 = scp[nl], s1v = scp[nl + 1];
            const float i0 = bip[nl], i1 = bip[nl + 1];
            const float c0 = bcp[nl], c1 = bcp[nl + 1];
#pragma unroll
            for (int half = 0; half < 2; half++) {
                const int m = bm + wm + mt * 16 + g + half * 8;
                const float v0 = fmaxf(acc[mt][nt][2 * half]     + c0, 0.f) * s0  + i0;
                const float v1 = fmaxf(acc[mt][nt][2 * half + 1] + c1, 0.f) * s1v + i1;
                if (G == 1) {
                    const size_t o = (size_t)m * 2048 + 1024 + bn + nl;
                    *(uint32_t*)(g_a2 + o) = pk2h(__float2half_rn(v0), __float2half_rn(v1));
                } else {
                    *(float2*)(outp + (size_t)m * 512 + bn + nl) = make_float2(v0, v1);
                }
            }
        }
    }
}

// ---------------------------------------------------------------------------
extern "C" void kernel_launch(void* const* d_in, const int* in_sizes, int n_in,
                              void* d_out, int out_size) {
    const float* x   = (const float*)d_in[0];
    const float* q1  = (const float*)d_in[1];
    const float* q2  = (const float*)d_in[2];
    const float* w1  = (const float*)d_in[3];
    const float* b1  = (const float*)d_in[4];
    const float* w2  = (const float*)d_in[5];
    const float* b2  = (const float*)d_in[6];
    const float* wsk = (const float*)d_in[7];
    const float* bsk = (const float*)d_in[8];
    const float* s1  = (const float*)d_in[9];
    const float* bb1 = (const float*)d_in[10];
    const float* m1  = (const float*)d_in[11];
    const float* v1  = (const float*)d_in[12];
    const float* s2  = (const float*)d_in[13];
    const float* bb2 = (const float*)d_in[14];
    const float* m2  = (const float*)d_in[15];
    const float* v2  = (const float*)d_in[16];
    float* out = (float*)d_out;

    cudaFuncSetAttribute(mma_kernel<1>, cudaFuncAttributeMaxDynamicSharedMemorySize, SMEM_TOTAL);
    cudaFuncSetAttribute(mma_kernel<2>, cudaFuncAttributeMaxDynamicSharedMemorySize, SMEM_TOTAL);

    prep_w1_kernel<<<1024 * 1024 / 256, 256>>>(w1);
    prep_w2_kernel<<<512 * 3072 / 256, 256>>>(w2, wsk);
    conv_a1_kernel<<<BS * 1024 / 4 / 256, 256>>>(q1, x);
    conv_a2_kernel<<<BS * 1024 / 4 / 256, 256>>>(q2);

    mma_kernel<1><<<dim3(BS / 256, 8), 512, SMEM_TOTAL>>>(b1, s1, bb1, m1, v1, v1, nullptr);
    mma_kernel<2><<<dim3(BS / 256, 4), 512, SMEM_TOTAL>>>(b2, bsk, s2, bb2, m2, v2, out);
}

// round 5
// speedup vs baseline: 3.3506x; 1.0730x over previous
#include <cuda_runtime.h>
#include <cuda_fp16.h>
#include <cstdint>

#define BS   16384
#define EPSV 1e-5f

// ---------------------------------------------------------------------------
// Device scratch (no allocs allowed)
// ---------------------------------------------------------------------------
__device__ __half g_a1[(size_t)BS * 1024];   // [b][k] : q1_0 | x   (fp16)
__device__ __half g_a2[(size_t)BS * 2048];   // [b][k] : q2_0 | h1  (fp16)
__device__ __half g_w1[1024 * 1024];         // [n][k] de-interleaved
__device__ __half g_w2[512 * 3072];          // [n][k] w2|wsk combined

// ---------------------------------------------------------------------------
// Helpers
// ---------------------------------------------------------------------------
__device__ __forceinline__ uint32_t s2u(const void* p) {
    uint32_t a;
    asm("{ .reg .u64 t; cvta.to.shared.u64 t, %1; cvt.u32.u64 %0, t; }"
        : "=r"(a) : "l"(p));
    return a;
}
__device__ __forceinline__ void cp16(uint32_t saddr, const void* gptr) {
    asm volatile("cp.async.cg.shared.global [%0], [%1], 16;"
                 :: "r"(saddr), "l"(__cvta_generic_to_global(gptr)) : "memory");
}
#define CP_COMMIT() asm volatile("cp.async.commit_group;" ::: "memory")
#define CP_WAIT(n)  asm volatile("cp.async.wait_group %0;" :: "n"(n) : "memory")

__device__ __forceinline__ void ldmx4(uint32_t* r, uint32_t addr) {
    asm volatile("ldmatrix.sync.aligned.m8n8.x4.shared.b16 {%0,%1,%2,%3}, [%4];"
                 : "=r"(r[0]), "=r"(r[1]), "=r"(r[2]), "=r"(r[3]) : "r"(addr));
}
__device__ __forceinline__ void mma16816(float* d, const uint32_t* a,
                                         uint32_t b0, uint32_t b1) {
    asm volatile(
        "mma.sync.aligned.m16n8k16.row.col.f32.f16.f16.f32 "
        "{%0,%1,%2,%3}, {%4,%5,%6,%7}, {%8,%9}, {%0,%1,%2,%3};"
        : "+f"(d[0]), "+f"(d[1]), "+f"(d[2]), "+f"(d[3])
        : "r"(a[0]), "r"(a[1]), "r"(a[2]), "r"(a[3]), "r"(b0), "r"(b1));
}
__device__ __forceinline__ uint32_t pk2h(__half a, __half b) {
    __half2 t(a, b);
    return *reinterpret_cast<uint32_t*>(&t);
}

// ---------------------------------------------------------------------------
// Prep kernels
// ---------------------------------------------------------------------------
__global__ void conv_a1_kernel(const float* __restrict__ q1, const float* __restrict__ x) {
    int idx = blockIdx.x * 256 + threadIdx.x;       // 4 elems each
    int b = idx >> 8;
    int k4 = (idx & 255) << 2;
    const float* src = (k4 < 512) ? (q1 + (size_t)b * 512 + k4)
                                  : (x  + (size_t)b * 512 + k4 - 512);
    float4 v = *(const float4*)src;
    size_t o = (size_t)b * 1024 + k4;
    *(uint2*)(g_a1 + o) = make_uint2(pk2h(__float2half_rn(v.x), __float2half_rn(v.y)),
                                     pk2h(__float2half_rn(v.z), __float2half_rn(v.w)));
}
__global__ void conv_a2_kernel(const float* __restrict__ q2) {
    int idx = blockIdx.x * 256 + threadIdx.x;
    int b = idx >> 8;
    int k4 = (idx & 255) << 2;
    float4 v = *(const float4*)(q2 + (size_t)b * 1024 + k4);
    size_t o = (size_t)b * 2048 + k4;
    *(uint2*)(g_a2 + o) = make_uint2(pk2h(__float2half_rn(v.x), __float2half_rn(v.y)),
                                     pk2h(__float2half_rn(v.z), __float2half_rn(v.w)));
}
__global__ void prep_w1_kernel(const float* __restrict__ w1) {
    int idx = blockIdx.x * 256 + threadIdx.x;       // n*1024 + k
    int n = idx >> 10, k = idx & 1023;
    int src = (k < 512) ? (2 * k) : (2 * (k - 512) + 1);
    g_w1[idx] = __float2half_rn(w1[(size_t)n * 1024 + src]);
}
__global__ void prep_w2_kernel(const float* __restrict__ w2, const float* __restrict__ wsk) {
    int idx = blockIdx.x * 256 + threadIdx.x;       // n*3072 + k
    int n = idx / 3072, k = idx - n * 3072;
    float v;
    if (k < 1024)      v = w2 [(size_t)n * 2048 + 2 * k];
    else if (k < 2048) v = w2 [(size_t)n * 2048 + 2 * (k - 1024) + 1];
    else if (k < 2560) v = wsk[(size_t)n * 1024 + 2 * (k - 2048)];
    else               v = wsk[(size_t)n * 1024 + 2 * (k - 2560) + 1];
    g_w2[idx] = __float2half_rn(v);
}

// ---------------------------------------------------------------------------
// mma.sync GEMM: CTA 256x128, K-chunk 32, 16 warps (warp tile 64x32),
// 3-stage cp.async pipeline, one __syncthreads per chunk. Single fp16 pass.
// Stage: A[256][40] | B[128][40]   (30720 B/stage, pitch 80 B)
// ---------------------------------------------------------------------------
#define PITCH_B    80
#define A_BYTES    (256 * PITCH_B)
#define Bm_BYTES   (128 * PITCH_B)
#define STAGE_B    (A_BYTES + Bm_BYTES)
#define SMEM_TOTAL (3 * STAGE_B)

template<int G>
__global__ __launch_bounds__(512, 1)
void mma_kernel(const float* __restrict__ e0, const float* __restrict__ e1,
                const float* __restrict__ e2, const float* __restrict__ e3,
                const float* __restrict__ e4, const float* __restrict__ e5,
                float* __restrict__ outp)
{
    extern __shared__ char smem[];
    const uint32_t sbase = s2u(smem);
    const int tid  = threadIdx.x;
    const int wid  = tid >> 5, lane = tid & 31;
    const int bm   = blockIdx.x * 256;
    const int bn   = blockIdx.y * 128;
    const int wm   = (wid & 3) * 64;      // warp M offset
    const int wn   = (wid >> 2) * 32;     // warp N offset
    constexpr int NC = (G == 1) ? 32 : 96;

    float acc[4][4][4];
#pragma unroll
    for (int i = 0; i < 4; i++)
#pragma unroll
        for (int j = 0; j < 4; j++)
#pragma unroll
            for (int k = 0; k < 4; k++) acc[i][j][k] = 0.f;

    // ---- stage loader: 512 threads, 3 cp.async each ----
    const int lrow = tid >> 2;            // 0..127
    const int lch  = tid & 3;             // 16B chunk of the 64B k-data
    auto load_stage = [&](int s, int c) {
        const int k0 = c * 32;
        const __half* Aa;
        int astr, acol;
        if (G == 1)        { Aa = g_a1; astr = 1024; acol = k0; }
        else if (k0 < 2048){ Aa = g_a2; astr = 2048; acol = k0; }
        else               { Aa = g_a1; astr = 1024; acol = k0 - 2048; }
        const __half* Bw = (G == 1) ? g_w1 : g_w2;
        const int bstr = (G == 1) ? 1024 : 3072;
        const uint32_t st = sbase + s * STAGE_B;
        const uint32_t so = lrow * PITCH_B + lch * 16;
        cp16(st + so,
             Aa + (size_t)(bm + lrow) * astr + acol + lch * 8);
        cp16(st + so + 128 * PITCH_B,
             Aa + (size_t)(bm + lrow + 128) * astr + acol + lch * 8);
        cp16(st + A_BYTES + so,
             Bw + (size_t)(bn + lrow) * bstr + k0 + lch * 8);
    };

    // per-thread ldmatrix base offsets
    const int mrow = lane & 15, msel = lane >> 4;
    const uint32_t aoff = (wm + mrow) * PITCH_B + msel * 16;
    const uint32_t boff = (wn + mrow) * PITCH_B + msel * 16;

    load_stage(0, 0); CP_COMMIT();
    load_stage(1, 1); CP_COMMIT();

    int sc = 0;                            // stage index of chunk c
    for (int c = 0; c < NC; c++) {
        if (c + 1 < NC) { CP_WAIT(1); } else { CP_WAIT(0); }
        __syncthreads();
        if (c + 2 < NC) {
            int sn = sc + 2; if (sn >= 3) sn -= 3;
            load_stage(sn, c + 2);
            CP_COMMIT();
        }
        const uint32_t st = sbase + sc * STAGE_B;
#pragma unroll
        for (int ks = 0; ks < 2; ks++) {               // two k16 substeps
            const uint32_t kadd = ks * 32;             // 16 halfs = 32 B
            uint32_t bh[2][4];
#pragma unroll
            for (int p = 0; p < 2; p++)
                ldmx4(bh[p], st + A_BYTES + boff + p * 16 * PITCH_B + kadd);
#pragma unroll
            for (int mt = 0; mt < 4; mt++) {
                uint32_t ah[4];
                ldmx4(ah, st + aoff + mt * 16 * PITCH_B + kadd);
#pragma unroll
                for (int nt = 0; nt < 4; nt++) {
                    const int p = nt >> 1, o = nt & 1;
                    mma16816(acc[mt][nt], ah, bh[p][o], bh[p][2 + o]);
                }
            }
        }
        if (++sc == 3) sc = 0;
    }
    __syncthreads();

    // ---- epilogue: stage per-column params, then write ----
    if (tid < 128) {
        const int n = bn + tid;
        float s, bi, bc;
        if (G == 1) { s = e1[n] * rsqrtf(e4[n] + EPSV); bi = e2[n] - e3[n] * s; bc = e0[n]; }
        else        { s = e2[n] * rsqrtf(e5[n] + EPSV); bi = e3[n] - e4[n] * s; bc = e0[n] + e1[n]; }
        ((float*)smem)[tid]       = s;
        ((float*)smem)[128 + tid] = bi;
        ((float*)smem)[256 + tid] = bc;
    }
    __syncthreads();
    const float* scp = (const float*)smem;
    const float* bip = scp + 128;
    const float* bcp = scp + 256;

    const int g  = lane >> 2, tg = lane & 3;
#pragma unroll
    for (int mt = 0; mt < 4; mt++) {
#pragma unroll
        for (int nt = 0; nt < 4; nt++) {
            const int nl = wn + nt * 8 + 2 * tg;       // CTA-local col (even)
            const float s0 = scp[nl], s1v = scp[nl + 1];
            const float i0 = bip[nl], i1 = bip[nl + 1];
            const float c0 = bcp[nl], c1 = bcp[nl + 1];
#pragma unroll
            for (int half = 0; half < 2; half++) {
                const int m = bm + wm + mt * 16 + g + half * 8;
                const float v0 = fmaxf(acc[mt][nt][2 * half]     + c0, 0.f) * s0  + i0;
                const float v1 = fmaxf(acc[mt][nt][2 * half + 1] + c1, 0.f) * s1v + i1;
                if (G == 1) {
                    const size_t o = (size_t)m * 2048 + 1024 + bn + nl;
                    *(uint32_t*)(g_a2 + o) = pk2h(__float2half_rn(v0), __float2half_rn(v1));
                } else {
                    *(float2*)(outp + (size_t)m * 512 + bn + nl) = make_float2(v0, v1);
                }
            }
        }
    }
}

// ---------------------------------------------------------------------------
extern "C" void kernel_launch(void* const* d_in, const int* in_sizes, int n_in,
                              void* d_out, int out_size) {
    const float* x   = (const float*)d_in[0];
    const float* q1  = (const float*)d_in[1];
    const float* q2  = (const float*)d_in[2];
    const float* w1  = (const float*)d_in[3];
    const float* b1  = (const float*)d_in[4];
    const float* w2  = (const float*)d_in[5];
    const float* b2  = (const float*)d_in[6];
    const float* wsk = (const float*)d_in[7];
    const float* bsk = (const float*)d_in[8];
    const float* s1  = (const float*)d_in[9];
    const float* bb1 = (const float*)d_in[10];
    const float* m1  = (const float*)d_in[11];
    const float* v1  = (const float*)d_in[12];
    const float* s2  = (const float*)d_in[13];
    const float* bb2 = (const float*)d_in[14];
    const float* m2  = (const float*)d_in[15];
    const float* v2  = (const float*)d_in[16];
    float* out = (float*)d_out;

    cudaFuncSetAttribute(mma_kernel<1>, cudaFuncAttributeMaxDynamicSharedMemorySize, SMEM_TOTAL);
    cudaFuncSetAttribute(mma_kernel<2>, cudaFuncAttributeMaxDynamicSharedMemorySize, SMEM_TOTAL);

    prep_w1_kernel<<<1024 * 1024 / 256, 256>>>(w1);
    prep_w2_kernel<<<512 * 3072 / 256, 256>>>(w2, wsk);
    conv_a1_kernel<<<BS * 1024 / 4 / 256, 256>>>(q1, x);
    conv_a2_kernel<<<BS * 1024 / 4 / 256, 256>>>(q2);

    mma_kernel<1><<<dim3(BS / 256, 8), 512, SMEM_TOTAL>>>(b1, s1, bb1, m1, v1, v1, nullptr);
    mma_kernel<2><<<dim3(BS / 256, 4), 512, SMEM_TOTAL>>>(b2, bsk, s2, bb2, m2, v2, out);
}

// round 6
// speedup vs baseline: 5.3416x; 1.5942x over previous
#include <cuda_runtime.h>
#include <cuda_fp16.h>
#include <cstdint>

#define BS   16384
#define EPSV 1e-5f

// ---------------------------------------------------------------------------
// Device scratch (no allocs allowed)
// ---------------------------------------------------------------------------
__device__ __half g_a1[(size_t)BS * 1024];   // [b][k] : q1_0 | x   (fp16)
__device__ __half g_a2[(size_t)BS * 2048];   // [b][k] : q2_0 | h1  (fp16)
__device__ __half g_w1[1024 * 1024];         // [n][k] de-interleaved
__device__ __half g_w2[512 * 3072];          // [n][k] w2|wsk combined

// ---------------------------------------------------------------------------
// Helpers
// ---------------------------------------------------------------------------
__device__ __forceinline__ uint32_t s2u(const void* p) {
    uint32_t a;
    asm("{ .reg .u64 t; cvta.to.shared.u64 t, %1; cvt.u32.u64 %0, t; }"
        : "=r"(a) : "l"(p));
    return a;
}
__device__ __forceinline__ void cp16(uint32_t saddr, const void* gptr) {
    asm volatile("cp.async.cg.shared.global [%0], [%1], 16;"
                 :: "r"(saddr), "l"(__cvta_generic_to_global(gptr)) : "memory");
}
#define CP_COMMIT() asm volatile("cp.async.commit_group;" ::: "memory")
#define CP_WAIT(n)  asm volatile("cp.async.wait_group %0;" :: "n"(n) : "memory")

__device__ __forceinline__ void ldmx4(uint32_t* r, uint32_t addr) {
    asm volatile("ldmatrix.sync.aligned.m8n8.x4.shared.b16 {%0,%1,%2,%3}, [%4];"
                 : "=r"(r[0]), "=r"(r[1]), "=r"(r[2]), "=r"(r[3]) : "r"(addr));
}
__device__ __forceinline__ void mma16816(float* d, const uint32_t* a,
                                         uint32_t b0, uint32_t b1) {
    asm volatile(
        "mma.sync.aligned.m16n8k16.row.col.f32.f16.f16.f32 "
        "{%0,%1,%2,%3}, {%4,%5,%6,%7}, {%8,%9}, {%0,%1,%2,%3};"
        : "+f"(d[0]), "+f"(d[1]), "+f"(d[2]), "+f"(d[3])
        : "r"(a[0]), "r"(a[1]), "r"(a[2]), "r"(a[3]), "r"(b0), "r"(b1));
}
__device__ __forceinline__ uint32_t pk2h(__half a, __half b) {
    __half2 t(a, b);
    return *reinterpret_cast<uint32_t*>(&t);
}

// ---------------------------------------------------------------------------
// Prep kernels
// ---------------------------------------------------------------------------
__global__ void conv_a1_kernel(const float* __restrict__ q1, const float* __restrict__ x) {
    int idx = blockIdx.x * 256 + threadIdx.x;       // 4 elems each
    int b = idx >> 8;
    int k4 = (idx & 255) << 2;
    const float* src = (k4 < 512) ? (q1 + (size_t)b * 512 + k4)
                                  : (x  + (size_t)b * 512 + k4 - 512);
    float4 v = *(const float4*)src;
    size_t o = (size_t)b * 1024 + k4;
    *(uint2*)(g_a1 + o) = make_uint2(pk2h(__float2half_rn(v.x), __float2half_rn(v.y)),
                                     pk2h(__float2half_rn(v.z), __float2half_rn(v.w)));
}
__global__ void conv_a2_kernel(const float* __restrict__ q2) {
    int idx = blockIdx.x * 256 + threadIdx.x;
    int b = idx >> 8;
    int k4 = (idx & 255) << 2;
    float4 v = *(const float4*)(q2 + (size_t)b * 1024 + k4);
    size_t o = (size_t)b * 2048 + k4;
    *(uint2*)(g_a2 + o) = make_uint2(pk2h(__float2half_rn(v.x), __float2half_rn(v.y)),
                                     pk2h(__float2half_rn(v.z), __float2half_rn(v.w)));
}
__global__ void prep_w1_kernel(const float* __restrict__ w1) {
    int idx = blockIdx.x * 256 + threadIdx.x;       // n*1024 + k
    int n = idx >> 10, k = idx & 1023;
    int src = (k < 512) ? (2 * k) : (2 * (k - 512) + 1);
    g_w1[idx] = __float2half_rn(w1[(size_t)n * 1024 + src]);
}
__global__ void prep_w2_kernel(const float* __restrict__ w2, const float* __restrict__ wsk) {
    int idx = blockIdx.x * 256 + threadIdx.x;       // n*3072 + k
    int n = idx / 3072, k = idx - n * 3072;
    float v;
    if (k < 1024)      v = w2 [(size_t)n * 2048 + 2 * k];
    else if (k < 2048) v = w2 [(size_t)n * 2048 + 2 * (k - 1024) + 1];
    else if (k < 2560) v = wsk[(size_t)n * 1024 + 2 * (k - 2048)];
    else               v = wsk[(size_t)n * 1024 + 2 * (k - 2560) + 1];
    g_w2[idx] = __float2half_rn(v);
}

// ---------------------------------------------------------------------------
// mma.sync GEMM: CTA 128x128, K-chunk 32, 8 warps (warp tile 64x32),
// 3-stage cp.async pipeline, 2 CTAs/SM. Single fp16 pass.
// Stage: A[128][40] | B[128][40]  (20480 B/stage, pitch 80B)
// ---------------------------------------------------------------------------
#define PITCH_B    80
#define A_BYTES    (128 * PITCH_B)
#define Bm_BYTES   (128 * PITCH_B)
#define STAGE_B    (A_BYTES + Bm_BYTES)
#define SMEM_TOTAL (3 * STAGE_B)

template<int G>
__global__ __launch_bounds__(256, 2)
void mma_kernel(const float* __restrict__ e0, const float* __restrict__ e1,
                const float* __restrict__ e2, const float* __restrict__ e3,
                const float* __restrict__ e4, const float* __restrict__ e5,
                float* __restrict__ outp)
{
    extern __shared__ char smem[];
    const uint32_t sbase = s2u(smem);
    const int tid  = threadIdx.x;
    const int wid  = tid >> 5, lane = tid & 31;
    const int bm   = blockIdx.x * 128;
    const int bn   = blockIdx.y * 128;
    const int wm   = (wid & 1) * 64;      // warp M offset
    const int wn   = (wid >> 1) * 32;     // warp N offset
    constexpr int NC = (G == 1) ? 32 : 96;

    float acc[4][4][4];
#pragma unroll
    for (int i = 0; i < 4; i++)
#pragma unroll
        for (int j = 0; j < 4; j++)
#pragma unroll
            for (int k = 0; k < 4; k++) acc[i][j][k] = 0.f;

    // ---- stage loader: 256 threads, 4 cp.async each ----
    const int lrow = tid >> 2;            // 0..63
    const int lch  = tid & 3;             // 16B chunk of the 64B k-data
    auto load_stage = [&](int s, int c) {
        const int k0 = c * 32;
        const __half* Aa;
        int astr, acol;
        if (G == 1)        { Aa = g_a1; astr = 1024; acol = k0; }
        else if (k0 < 2048){ Aa = g_a2; astr = 2048; acol = k0; }
        else               { Aa = g_a1; astr = 1024; acol = k0 - 2048; }
        const __half* Bw = (G == 1) ? g_w1 : g_w2;
        const int bstr = (G == 1) ? 1024 : 3072;
        const uint32_t st = sbase + s * STAGE_B;
        const uint32_t so = lrow * PITCH_B + lch * 16;
#pragma unroll
        for (int it = 0; it < 2; it++) {
            const int row = lrow + it * 64;
            cp16(st + so + it * 64 * PITCH_B,
                 Aa + (size_t)(bm + row) * astr + acol + lch * 8);
            cp16(st + A_BYTES + so + it * 64 * PITCH_B,
                 Bw + (size_t)(bn + row) * bstr + k0 + lch * 8);
        }
    };

    // per-thread ldmatrix base offsets
    const int mrow = lane & 15, msel = lane >> 4;
    const uint32_t aoff = (wm + mrow) * PITCH_B + msel * 16;
    const uint32_t boff = (wn + mrow) * PITCH_B + msel * 16;

    load_stage(0, 0); CP_COMMIT();
    load_stage(1, 1); CP_COMMIT();

    int sc = 0;                            // stage index of chunk c
    for (int c = 0; c < NC; c++) {
        if (c + 1 < NC) { CP_WAIT(1); } else { CP_WAIT(0); }
        __syncthreads();
        if (c + 2 < NC) {
            int sn = sc + 2; if (sn >= 3) sn -= 3;
            load_stage(sn, c + 2);
            CP_COMMIT();
        }
        const uint32_t st = sbase + sc * STAGE_B;
#pragma unroll
        for (int ks = 0; ks < 2; ks++) {               // two k16 substeps
            const uint32_t kadd = ks * 32;             // 16 halfs = 32 B
            uint32_t bh[2][4];
#pragma unroll
            for (int p = 0; p < 2; p++)
                ldmx4(bh[p], st + A_BYTES + boff + p * 16 * PITCH_B + kadd);
#pragma unroll
            for (int mt = 0; mt < 4; mt++) {
                uint32_t ah[4];
                ldmx4(ah, st + aoff + mt * 16 * PITCH_B + kadd);
#pragma unroll
                for (int nt = 0; nt < 4; nt++) {
                    const int p = nt >> 1, o = nt & 1;
                    mma16816(acc[mt][nt], ah, bh[p][o], bh[p][2 + o]);
                }
            }
        }
        if (++sc == 3) sc = 0;
    }
    __syncthreads();

    // ---- epilogue: stage per-column params, then write ----
    if (tid < 128) {
        const int n = bn + tid;
        float s, bi, bc;
        if (G == 1) { s = e1[n] * rsqrtf(e4[n] + EPSV); bi = e2[n] - e3[n] * s; bc = e0[n]; }
        else        { s = e2[n] * rsqrtf(e5[n] + EPSV); bi = e3[n] - e4[n] * s; bc = e0[n] + e1[n]; }
        ((float*)smem)[tid]       = s;
        ((float*)smem)[128 + tid] = bi;
        ((float*)smem)[256 + tid] = bc;
    }
    __syncthreads();
    const float* scp = (const float*)smem;
    const float* bip = scp + 128;
    const float* bcp = scp + 256;

    const int g  = lane >> 2, tg = lane & 3;
#pragma unroll
    for (int mt = 0; mt < 4; mt++) {
#pragma unroll
        for (int nt = 0; nt < 4; nt++) {
            const int nl = wn + nt * 8 + 2 * tg;       // CTA-local col (even)
            const float s0 = scp[nl], s1v = scp[nl + 1];
            const float i0 = bip[nl], i1 = bip[nl + 1];
            const float c0 = bcp[nl], c1 = bcp[nl + 1];
#pragma unroll
            for (int half = 0; half < 2; half++) {
                const int m = bm + wm + mt * 16 + g + half * 8;
                const float v0 = fmaxf(acc[mt][nt][2 * half]     + c0, 0.f) * s0  + i0;
                const float v1 = fmaxf(acc[mt][nt][2 * half + 1] + c1, 0.f) * s1v + i1;
                if (G == 1) {
                    const size_t o = (size_t)m * 2048 + 1024 + bn + nl;
                    *(uint32_t*)(g_a2 + o) = pk2h(__float2half_rn(v0), __float2half_rn(v1));
                } else {
                    *(float2*)(outp + (size_t)m * 512 + bn + nl) = make_float2(v0, v1);
                }
            }
        }
    }
}

// ---------------------------------------------------------------------------
extern "C" void kernel_launch(void* const* d_in, const int* in_sizes, int n_in,
                              void* d_out, int out_size) {
    const float* x   = (const float*)d_in[0];
    const float* q1  = (const float*)d_in[1];
    const float* q2  = (const float*)d_in[2];
    const float* w1  = (const float*)d_in[3];
    const float* b1  = (const float*)d_in[4];
    const float* w2  = (const float*)d_in[5];
    const float* b2  = (const float*)d_in[6];
    const float* wsk = (const float*)d_in[7];
    const float* bsk = (const float*)d_in[8];
    const float* s1  = (const float*)d_in[9];
    const float* bb1 = (const float*)d_in[10];
    const float* m1  = (const float*)d_in[11];
    const float* v1  = (const float*)d_in[12];
    const float* s2  = (const float*)d_in[13];
    const float* bb2 = (const float*)d_in[14];
    const float* m2  = (const float*)d_in[15];
    const float* v2  = (const float*)d_in[16];
    float* out = (float*)d_out;

    cudaFuncSetAttribute(mma_kernel<1>, cudaFuncAttributeMaxDynamicSharedMemorySize, SMEM_TOTAL);
    cudaFuncSetAttribute(mma_kernel<2>, cudaFuncAttributeMaxDynamicSharedMemorySize, SMEM_TOTAL);

    prep_w1_kernel<<<1024 * 1024 / 256, 256>>>(w1);
    prep_w2_kernel<<<512 * 3072 / 256, 256>>>(w2, wsk);
    conv_a1_kernel<<<BS * 1024 / 4 / 256, 256>>>(q1, x);
    conv_a2_kernel<<<BS * 1024 / 4 / 256, 256>>>(q2);

    mma_kernel<1><<<dim3(BS / 128, 8), 256, SMEM_TOTAL>>>(b1, s1, bb1, m1, v1, v1, nullptr);
    mma_kernel<2><<<dim3(BS / 128, 4), 256, SMEM_TOTAL>>>(b2, bsk, s2, bb2, m2, v2, out);
}

// round 7
// speedup vs baseline: 5.8546x; 1.0960x over previous
#include <cuda_runtime.h>
#include <cuda_fp16.h>
#include <cstdint>

#define BS   16384
#define EPSV 1e-5f

// ---------------------------------------------------------------------------
// Device scratch (no allocs allowed)
// ---------------------------------------------------------------------------
__device__ __half g_a1[(size_t)BS * 1024];   // [b][k] : q1_0 | x   (fp16)
__device__ __half g_a2[(size_t)BS * 2048];   // [b][k] : q2_0 | h1  (fp16)
__device__ __half g_w1[1024 * 1024];         // [n][k] de-interleaved
__device__ __half g_w2[512 * 3072];          // [n][k] w2|wsk combined
__device__ int    g_tile;                    // global tile counter
__device__ int    g_rowcnt[128];             // gemm1 completions per M-row-block

// ---------------------------------------------------------------------------
// Helpers
// ---------------------------------------------------------------------------
__device__ __forceinline__ uint32_t s2u(const void* p) {
    uint32_t a;
    asm("{ .reg .u64 t; cvta.to.shared.u64 t, %1; cvt.u32.u64 %0, t; }"
        : "=r"(a) : "l"(p));
    return a;
}
__device__ __forceinline__ void cp16(uint32_t saddr, const void* gptr) {
    asm volatile("cp.async.cg.shared.global [%0], [%1], 16;"
                 :: "r"(saddr), "l"(__cvta_generic_to_global(gptr)) : "memory");
}
#define CP_COMMIT() asm volatile("cp.async.commit_group;" ::: "memory")
#define CP_WAIT(n)  asm volatile("cp.async.wait_group %0;" :: "n"(n) : "memory")

__device__ __forceinline__ void ldmx4(uint32_t* r, uint32_t addr) {
    asm volatile("ldmatrix.sync.aligned.m8n8.x4.shared.b16 {%0,%1,%2,%3}, [%4];"
                 : "=r"(r[0]), "=r"(r[1]), "=r"(r[2]), "=r"(r[3]) : "r"(addr));
}
__device__ __forceinline__ void mma16816(float* d, const uint32_t* a,
                                         uint32_t b0, uint32_t b1) {
    asm volatile(
        "mma.sync.aligned.m16n8k16.row.col.f32.f16.f16.f32 "
        "{%0,%1,%2,%3}, {%4,%5,%6,%7}, {%8,%9}, {%0,%1,%2,%3};"
        : "+f"(d[0]), "+f"(d[1]), "+f"(d[2]), "+f"(d[3])
        : "r"(a[0]), "r"(a[1]), "r"(a[2]), "r"(a[3]), "r"(b0), "r"(b1));
}
__device__ __forceinline__ uint32_t pk2h(__half a, __half b) {
    __half2 t(a, b);
    return *reinterpret_cast<uint32_t*>(&t);
}
__device__ __forceinline__ int ld_acq(const int* p) {
    int v;
    asm volatile("ld.acquire.gpu.global.b32 %0, [%1];"
                 : "=r"(v) : "l"(p) : "memory");
    return v;
}

// ---------------------------------------------------------------------------
// Merged prep kernel: a1 conv | a2 conv | w1 prep | w2 prep  (+ counter reset)
// ---------------------------------------------------------------------------
__global__ void prep_kernel(const float* __restrict__ q1, const float* __restrict__ x,
                            const float* __restrict__ q2,
                            const float* __restrict__ w1,
                            const float* __restrict__ w2, const float* __restrict__ wsk)
{
    const int bid = blockIdx.x;
    const int tid = threadIdx.x;
    if (bid == 0) {                               // reset scheduler state
        if (tid < 128) g_rowcnt[tid] = 0;
        if (tid == 128) g_tile = 0;
    }
    if (bid < 16384) {                            // a1: q1_0 | x  -> fp16
        int idx = bid * 256 + tid;
        int b = idx >> 8;
        int k4 = (idx & 255) << 2;
        const float* src = (k4 < 512) ? (q1 + (size_t)b * 512 + k4)
                                      : (x  + (size_t)b * 512 + k4 - 512);
        float4 v = *(const float4*)src;
        size_t o = (size_t)b * 1024 + k4;
        *(uint2*)(g_a1 + o) = make_uint2(pk2h(__float2half_rn(v.x), __float2half_rn(v.y)),
                                         pk2h(__float2half_rn(v.z), __float2half_rn(v.w)));
    } else if (bid < 32768) {                     // a2 cols 0..1023: q2_0 -> fp16
        int idx = (bid - 16384) * 256 + tid;
        int b = idx >> 8;
        int k4 = (idx & 255) << 2;
        float4 v = *(const float4*)(q2 + (size_t)b * 1024 + k4);
        size_t o = (size_t)b * 2048 + k4;
        *(uint2*)(g_a2 + o) = make_uint2(pk2h(__float2half_rn(v.x), __float2half_rn(v.y)),
                                         pk2h(__float2half_rn(v.z), __float2half_rn(v.w)));
    } else if (bid < 36864) {                     // w1 de-interleave -> [n][k]
        int idx = (bid - 32768) * 256 + tid;
        int n = idx >> 10, k = idx & 1023;
        int src = (k < 512) ? (2 * k) : (2 * (k - 512) + 1);
        g_w1[idx] = __float2half_rn(w1[(size_t)n * 1024 + src]);
    } else {                                      // w2|wsk combined -> [n][k]
        int idx = (bid - 36864) * 256 + tid;
        int n = idx / 3072, k = idx - n * 3072;
        float v;
        if (k < 1024)      v = w2 [(size_t)n * 2048 + 2 * k];
        else if (k < 2048) v = w2 [(size_t)n * 2048 + 2 * (k - 1024) + 1];
        else if (k < 2560) v = wsk[(size_t)n * 1024 + 2 * (k - 2048)];
        else               v = wsk[(size_t)n * 1024 + 2 * (k - 2560) + 1];
        g_w2[idx] = __float2half_rn(v);
    }
}

// ---------------------------------------------------------------------------
// Fused persistent GEMM kernel.
// Tiles 0..1023  : gemm1 (bm = (t>>3)*128, bn = (t&7)*128), K=1024
// Tiles 1024..1535: gemm2 (bm = (u>>2)*128, bn = (u&3)*128), K=3072
// CTA 128x128, K-chunk 64, 2-stage double buffer, 8 warps (warp 64x32),
// pitch 144 B (conflict-free ldmatrix), 2 CTAs/SM.
// ---------------------------------------------------------------------------
#define PITCH      144
#define B_OFF      (128 * PITCH)
#define STAGE_B    (2 * 128 * PITCH)      // 36864
#define PARAM_OFF  (2 * STAGE_B)          // 73728
#define SMEM_TOTAL (PARAM_OFF + 2048)

__global__ __launch_bounds__(256, 2)
void fused_kernel(const float* __restrict__ b1, const float* __restrict__ s1,
                  const float* __restrict__ bb1, const float* __restrict__ m1,
                  const float* __restrict__ v1,
                  const float* __restrict__ b2, const float* __restrict__ bsk,
                  const float* __restrict__ s2, const float* __restrict__ bb2,
                  const float* __restrict__ m2, const float* __restrict__ v2,
                  float* __restrict__ outp)
{
    extern __shared__ char smem[];
    const uint32_t sbase = s2u(smem);
    const int tid  = threadIdx.x;
    const int wid  = tid >> 5, lane = tid & 31;
    const int wm   = (wid & 1) * 64;
    const int wn   = (wid >> 1) * 32;

    float* scp = (float*)(smem + PARAM_OFF);
    float* bip = scp + 128;
    float* bcp = scp + 256;
    int*  tilep = (int*)(smem + PARAM_OFF + 1536);

    const int mrow = lane & 15, msel = lane >> 4;
    const uint32_t aoff = (wm + mrow) * PITCH + msel * 16;
    const uint32_t boff = (wn + mrow) * PITCH + msel * 16;
    const int g  = lane >> 2, tg = lane & 3;

    for (;;) {
        if (tid == 0) *tilep = atomicAdd(&g_tile, 1);
        __syncthreads();
        const int t = *tilep;
        if (t >= 1536) break;

        const bool g1 = (t < 1024);
        int bm, bn, NC;
        if (g1) { bm = (t >> 3) * 128;          bn = (t & 7) * 128; NC = 16; }
        else    { int u = t - 1024; bm = (u >> 2) * 128; bn = (u & 3) * 128; NC = 48; }
        const __half* Bw = g1 ? g_w1 : g_w2;
        const int bstr   = g1 ? 1024 : 3072;

        if (!g1) {                        // wait for h1 rows [bm, bm+128)
            if (tid == 0) {
                const int* cp = &g_rowcnt[bm >> 7];
                while (ld_acq(cp) < 8) __nanosleep(128);
            }
            __syncthreads();
        }

        float acc[4][4][4];
#pragma unroll
        for (int i = 0; i < 4; i++)
#pragma unroll
            for (int j = 0; j < 4; j++)
#pragma unroll
                for (int k = 0; k < 4; k++) acc[i][j][k] = 0.f;

        auto load_stage = [&](int slot, int c) {
            const int k0 = c * 64;
            const __half* Aa; int astr, acol;
            if (g1)             { Aa = g_a1; astr = 1024; acol = k0; }
            else if (k0 < 2048) { Aa = g_a2; astr = 2048; acol = k0; }
            else                { Aa = g_a1; astr = 1024; acol = k0 - 2048; }
            const uint32_t st = sbase + slot * STAGE_B;
#pragma unroll
            for (int j = 0; j < 4; j++) {
                int idx = j * 256 + tid;
                int row = idx >> 3, ch = idx & 7;
                cp16(st + row * PITCH + ch * 16,
                     Aa + (size_t)(bm + row) * astr + acol + ch * 8);
                cp16(st + B_OFF + row * PITCH + ch * 16,
                     Bw + (size_t)(bn + row) * bstr + k0 + ch * 8);
            }
        };

        load_stage(0, 0); CP_COMMIT();

        for (int c = 0; c < NC; c++) {
            CP_WAIT(0);
            __syncthreads();
            if (c + 1 < NC) { load_stage((c + 1) & 1, c + 1); CP_COMMIT(); }
            const uint32_t st = sbase + (c & 1) * STAGE_B;
#pragma unroll
            for (int ks = 0; ks < 4; ks++) {           // four k16 substeps
                const uint32_t kadd = ks * 32;
                uint32_t bh[2][4];
#pragma unroll
                for (int p = 0; p < 2; p++)
                    ldmx4(bh[p], st + B_OFF + boff + p * 16 * PITCH + kadd);
#pragma unroll
                for (int mt = 0; mt < 4; mt++) {
                    uint32_t ah[4];
                    ldmx4(ah, st + aoff + mt * 16 * PITCH + kadd);
#pragma unroll
                    for (int nt = 0; nt < 4; nt++) {
                        const int p = nt >> 1, o = nt & 1;
                        mma16816(acc[mt][nt], ah, bh[p][o], bh[p][2 + o]);
                    }
                }
            }
        }

        // ---- epilogue: stage per-column params, then write ----
        if (tid < 128) {
            const int n = bn + tid;
            float s, bi, bc;
            if (g1) { s = s1[n] * rsqrtf(v1[n] + EPSV); bi = bb1[n] - m1[n] * s; bc = b1[n]; }
            else    { s = s2[n] * rsqrtf(v2[n] + EPSV); bi = bb2[n] - m2[n] * s; bc = b2[n] + bsk[n]; }
            scp[tid] = s; bip[tid] = bi; bcp[tid] = bc;
        }
        __syncthreads();        // also separates last chunk's smem reads

#pragma unroll
        for (int mt = 0; mt < 4; mt++) {
#pragma unroll
            for (int nt = 0; nt < 4; nt++) {
                const int nl = wn + nt * 8 + 2 * tg;
                const float s0 = scp[nl], s1v = scp[nl + 1];
                const float i0 = bip[nl], i1 = bip[nl + 1];
                const float c0 = bcp[nl], c1 = bcp[nl + 1];
#pragma unroll
                for (int half = 0; half < 2; half++) {
                    const int m = bm + wm + mt * 16 + g + half * 8;
                    const float v0 = fmaxf(acc[mt][nt][2 * half]     + c0, 0.f) * s0  + i0;
                    const float v1e = fmaxf(acc[mt][nt][2 * half + 1] + c1, 0.f) * s1v + i1;
                    if (g1) {
                        const size_t o = (size_t)m * 2048 + 1024 + bn + nl;
                        *(uint32_t*)(g_a2 + o) = pk2h(__float2half_rn(v0), __float2half_rn(v1e));
                    } else {
                        *(float2*)(outp + (size_t)m * 512 + bn + nl) = make_float2(v0, v1e);
                    }
                }
            }
        }

        if (g1) {               // publish h1 row-block completion
            __threadfence();
            __syncthreads();
            if (tid == 0) atomicAdd(&g_rowcnt[bm >> 7], 1);
        }
    }
}

// ---------------------------------------------------------------------------
extern "C" void kernel_launch(void* const* d_in, const int* in_sizes, int n_in,
                              void* d_out, int out_size) {
    const float* x   = (const float*)d_in[0];
    const float* q1  = (const float*)d_in[1];
    const float* q2  = (const float*)d_in[2];
    const float* w1  = (const float*)d_in[3];
    const float* b1  = (const float*)d_in[4];
    const float* w2  = (const float*)d_in[5];
    const float* b2  = (const float*)d_in[6];
    const float* wsk = (const float*)d_in[7];
    const float* bsk = (const float*)d_in[8];
    const float* s1  = (const float*)d_in[9];
    const float* bb1 = (const float*)d_in[10];
    const float* m1  = (const float*)d_in[11];
    const float* v1  = (const float*)d_in[12];
    const float* s2  = (const float*)d_in[13];
    const float* bb2 = (const float*)d_in[14];
    const float* m2  = (const float*)d_in[15];
    const float* v2  = (const float*)d_in[16];
    float* out = (float*)d_out;

    cudaFuncSetAttribute(fused_kernel, cudaFuncAttributeMaxDynamicSharedMemorySize, SMEM_TOTAL);

    // 16384 (a1) + 16384 (a2) + 4096 (w1) + 6144 (w2) blocks
    prep_kernel<<<43008, 256>>>(q1, x, q2, w1, w2, wsk);
    fused_kernel<<<296, 256, SMEM_TOTAL>>>(b1, s1, bb1, m1, v1,
                                           b2, bsk, s2, bb2, m2, v2, out);
}